// round 15
// baseline (speedup 1.0000x reference)
#include <cuda_runtime.h>
#include <cuda_fp16.h>
#include <cstdint>

#define NN 50000
#define NF 128
#define NE 600000
#define NR 2
#define NSEG (NN * NR)          // 100000
#define SCAN_BLKS 98            // ceil(NSEG / 1024)
#define KW 768                  // weight buffer K: [hi 384 | lo 384] fp16
#define NCH 12                  // 12 chunks of K=32

// ---------------- scratch (device globals; no allocation allowed) ----------
__device__ float g_h[(size_t)NN * NF];
__device__ unsigned short g_inh[(size_t)NN * NF];   // fp16 copy of layer input
__device__ float g_stats[2 * NF];
__device__ int   g_deg[NSEG];
__device__ int   g_cursor[NSEG];
__device__ float g_icnt[NSEG];
__device__ int   g_csr[NE];
__device__ int   g_bsum[128];
// fp16 operands (A side: hi only; B side: hi+lo)
__device__ unsigned short g_hhi[(size_t)NN * NF];
__device__ unsigned short g_mhi[(size_t)NN * NR * NF];
__device__ unsigned short g_wb[(size_t)4 * NF * KW];   // [layer][n=128][hi384|lo384]

// ---------------- helpers ---------------------------------------------------
__device__ __forceinline__ uint32_t smem_u32(const void* p) {
    uint32_t a;
    asm("{ .reg .u64 t; cvta.to.shared.u64 t, %1; cvt.u32.u64 %0, t; }"
        : "=r"(a) : "l"(p));
    return a;
}
#define SWZ64(off) ((off) ^ (((off) >> 3) & 0x30))
#define CP_ASYNC16(sm, gp) \
    asm volatile("cp.async.cg.shared.global [%0], [%1], 16;" :: "r"(sm), "l"(gp) : "memory")
#define CP_COMMIT() asm volatile("cp.async.commit_group;" ::: "memory")
#define CP_WAIT0()  asm volatile("cp.async.wait_group 0;" ::: "memory")

static __device__ __forceinline__ unsigned short hfu(float f) {
    __half h = __float2half_rn(f);
    return *(unsigned short*)&h;
}
static __device__ __forceinline__ float hff(unsigned short u) {
    __half h = *(__half*)&u;
    return __half2float(h);
}
static __device__ __forceinline__ uint2 pack4h(float4 v) {
    uint2 o;
    o.x = (uint32_t)hfu(v.x) | ((uint32_t)hfu(v.y) << 16);
    o.y = (uint32_t)hfu(v.z) | ((uint32_t)hfu(v.w) << 16);
    return o;
}
// accumulate 8 fp16 values (uint4) into fa[8]
static __device__ __forceinline__ void acc8h(float* fa, uint4 u) {
    const __half2* hp = (const __half2*)&u;
    float2 f0 = __half22float2(hp[0]);
    float2 f1 = __half22float2(hp[1]);
    float2 f2 = __half22float2(hp[2]);
    float2 f3 = __half22float2(hp[3]);
    fa[0] += f0.x; fa[1] += f0.y; fa[2] += f1.x; fa[3] += f1.y;
    fa[4] += f2.x; fa[5] += f2.y; fa[6] += f3.x; fa[7] += f3.y;
}

// ---------------------------------------------------------------------------
// CSR build (once per launch)
// ---------------------------------------------------------------------------
__global__ void hist_kernel(const int* __restrict__ dst, const int* __restrict__ et) {
    const int e = blockIdx.x * blockDim.x + threadIdx.x;
    if (e >= NE) return;
    atomicAdd(&g_deg[dst[e] * NR + et[e]], 1);
}
__global__ void scan1_kernel() {
    __shared__ int sh[256];
    const int t = threadIdx.x;
    const int base = blockIdx.x * 1024 + t * 4;
    int v[4];
#pragma unroll
    for (int k = 0; k < 4; k++) v[k] = (base + k < NSEG) ? g_deg[base + k] : 0;
    int sum = v[0] + v[1] + v[2] + v[3];
    sh[t] = sum;
    __syncthreads();
#pragma unroll
    for (int off = 1; off < 256; off <<= 1) {
        int add = (t >= off) ? sh[t - off] : 0;
        __syncthreads();
        sh[t] += add;
        __syncthreads();
    }
    int ex = sh[t] - sum;
#pragma unroll
    for (int k = 0; k < 4; k++) {
        if (base + k < NSEG) g_cursor[base + k] = ex;
        ex += v[k];
    }
    if (t == 255) g_bsum[blockIdx.x] = sh[255];
}
__global__ void scan2_kernel() {
    __shared__ int sh[128];
    const int t = threadIdx.x;
    int v = (t < SCAN_BLKS) ? g_bsum[t] : 0;
    sh[t] = v;
    __syncthreads();
#pragma unroll
    for (int off = 1; off < 128; off <<= 1) {
        int add = (t >= off) ? sh[t - off] : 0;
        __syncthreads();
        sh[t] += add;
        __syncthreads();
    }
    if (t < SCAN_BLKS) g_bsum[t] = sh[t] - v;   // exclusive
}
__global__ void addoff_kernel() {
    const int i = blockIdx.x * blockDim.x + threadIdx.x;
    if (i >= NSEG) return;
    g_cursor[i] += g_bsum[i >> 10];
    g_icnt[i] = 1.0f / (float)max(g_deg[i], 1);
}
__global__ void fill_kernel(const int* __restrict__ src, const int* __restrict__ dst,
                            const int* __restrict__ et) {
    const int e = blockIdx.x * blockDim.x + threadIdx.x;
    if (e >= NE) return;
    const int pos = atomicAdd(&g_cursor[dst[e] * NR + et[e]], 1);
    g_csr[pos] = src[e];
}

// ---------------------------------------------------------------------------
// Weight prep (all 4 layers): g_wb[l][n][k<384: fp16hi(W); k>=384: fp16lo]
// ---------------------------------------------------------------------------
__global__ void wt_kernel(const float* __restrict__ W0rel, const float* __restrict__ W0root,
                          const float* __restrict__ Wsrel, const float* __restrict__ Wsroot) {
    const int gi = blockIdx.x * blockDim.x + threadIdx.x;
    if (gi >= 4 * NF * KW) return;
    const int l = gi / (NF * KW);
    const int i = gi % (NF * KW);
    const int n = i / KW;
    const int kp = i % KW;
    const int k = (kp < 384) ? kp : (kp - 384);
    const float* Wrel = (l == 0) ? W0rel : Wsrel + (size_t)(l - 1) * NR * NF * NF;
    const float* Wroot = (l == 0) ? W0root : Wsroot + (size_t)(l - 1) * NF * NF;
    const float w = (k < 256) ? Wrel[k * NF + n] : Wroot[(k - 256) * NF + n];
    const unsigned short hi = hfu(w);
    g_wb[gi] = (kp < 384) ? hi : hfu(w - hff(hi));
}

// ---------------------------------------------------------------------------
// layer-0: fp16 copy of input
// ---------------------------------------------------------------------------
__global__ void conv16_kernel(const float* __restrict__ in) {
    const int i = blockIdx.x * blockDim.x + threadIdx.x;   // uint2 (4 vals) index
    if (i >= NN * NF / 4) return;
    ((uint2*)g_inh)[i] = pack4h(((const float4*)in)[i]);
}

// ---------------------------------------------------------------------------
// Column stats for layer 0 input (later layers: stats from gemm epilogue)
// ---------------------------------------------------------------------------
__global__ void stats_kernel(const float* __restrict__ in) {
    __shared__ float ss[256], sq[256];
    const int tid = threadIdx.x;
    const int f = tid & 127;
    const int half = tid >> 7;
    float s = 0.f, s2 = 0.f;
    for (int r = blockIdx.x * 2 + half; r < NN; r += gridDim.x * 2) {
        float v = in[r * NF + f];
        s += v; s2 += v * v;
    }
    ss[tid] = s; sq[tid] = s2;
    __syncthreads();
    if (tid < 128) {
        atomicAdd(&g_stats[f], ss[tid] + ss[tid + 128]);
        atomicAdd(&g_stats[NF + f], sq[tid] + sq[tid + 128]);
    }
}

// ---------------------------------------------------------------------------
// Fused aggregation + BN, fp16 gather, 2 edges/iteration:
// lane = half*16 + fl. fl indexes one uint4 (8 features); half selects the
// even/odd edge of a pair. 16 LDG.128 per edge (was 32). Cross-half shfl
// merge, then lanes 0-15 apply BN affine to the mean and write fp16 rows.
// rel==0 warps also write BN(own row) as the root operand.
// ---------------------------------------------------------------------------
__global__ void agg_kernel() {
    const int seg = (blockIdx.x * blockDim.x + threadIdx.x) >> 5;
    const int lane = threadIdx.x & 31;
    if (seg >= NSEG) return;
    const int half = lane >> 4;
    const int fl = lane & 15;
    const int end = g_cursor[seg];
    const int deg = g_deg[seg];
    const int start = end - deg;
    float fa[8];
#pragma unroll
    for (int i = 0; i < 8; i++) fa[i] = 0.f;
    const uint4* inh4 = (const uint4*)g_inh;

    for (int base = start; base < end; base += 32) {
        const int nrem = end - base;
        const int cnt = (nrem < 32) ? nrem : 32;
        const int myid = (lane < cnt) ? __ldg(&g_csr[base + lane]) : 0;
        int e = 0;
        // 4 edges per iteration (2 per half-warp) — MLP 2 per lane
        for (; e + 4 <= cnt; e += 4) {
            const int i0 = __shfl_sync(0xffffffffu, myid, e + half);
            const int i1 = __shfl_sync(0xffffffffu, myid, e + 2 + half);
            const uint4 u0 = inh4[(size_t)i0 * 16 + fl];
            const uint4 u1 = inh4[(size_t)i1 * 16 + fl];
            acc8h(fa, u0);
            acc8h(fa, u1);
        }
        // tail: pairs with predication
        for (; e < cnt; e += 2) {
            const int idx = e + half;
            const int sidx = (idx < cnt) ? idx : (cnt - 1);
            const int id = __shfl_sync(0xffffffffu, myid, sidx);
            const uint4 u = inh4[(size_t)id * 16 + fl];
            if (idx < cnt) acc8h(fa, u);
        }
    }
    // merge odd-edge half into even half
#pragma unroll
    for (int i = 0; i < 8; i++)
        fa[i] += __shfl_down_sync(0xffffffffu, fa[i], 16);

    if (half == 0) {
        const float ic = g_icnt[seg];
        const float live = (deg > 0) ? 1.0f : 0.0f;
        const int f = fl * 8;
        const float invn = 1.0f / NN;
        const float4 st0 = *(const float4*)(g_stats + f);
        const float4 st1 = *(const float4*)(g_stats + f + 4);
        const float4 sq0 = *(const float4*)(g_stats + NF + f);
        const float4 sq1 = *(const float4*)(g_stats + NF + f + 4);
        float mu[8], rs[8];
        mu[0] = st0.x * invn; rs[0] = rsqrtf(sq0.x * invn - mu[0] * mu[0] + 1e-5f);
        mu[1] = st0.y * invn; rs[1] = rsqrtf(sq0.y * invn - mu[1] * mu[1] + 1e-5f);
        mu[2] = st0.z * invn; rs[2] = rsqrtf(sq0.z * invn - mu[2] * mu[2] + 1e-5f);
        mu[3] = st0.w * invn; rs[3] = rsqrtf(sq0.w * invn - mu[3] * mu[3] + 1e-5f);
        mu[4] = st1.x * invn; rs[4] = rsqrtf(sq1.x * invn - mu[4] * mu[4] + 1e-5f);
        mu[5] = st1.y * invn; rs[5] = rsqrtf(sq1.y * invn - mu[5] * mu[5] + 1e-5f);
        mu[6] = st1.z * invn; rs[6] = rsqrtf(sq1.z * invn - mu[6] * mu[6] + 1e-5f);
        mu[7] = st1.w * invn; rs[7] = rsqrtf(sq1.w * invn - mu[7] * mu[7] + 1e-5f);

        float o[8];
#pragma unroll
        for (int i = 0; i < 8; i++)
            o[i] = live * ((fa[i] * ic - mu[i]) * rs[i] + 1e-4f);
        uint4 ow;
        ow.x = (uint32_t)hfu(o[0]) | ((uint32_t)hfu(o[1]) << 16);
        ow.y = (uint32_t)hfu(o[2]) | ((uint32_t)hfu(o[3]) << 16);
        ow.z = (uint32_t)hfu(o[4]) | ((uint32_t)hfu(o[5]) << 16);
        ow.w = (uint32_t)hfu(o[6]) | ((uint32_t)hfu(o[7]) << 16);
        ((uint4*)g_mhi)[(size_t)seg * 16 + fl] = ow;

        if ((seg & 1) == 0) {
            const int node = seg >> 1;
            const uint4 u = inh4[(size_t)node * 16 + fl];
            float rv[8];
            {
                const __half2* hp = (const __half2*)&u;
                float2 f0 = __half22float2(hp[0]);
                float2 f1 = __half22float2(hp[1]);
                float2 f2 = __half22float2(hp[2]);
                float2 f3 = __half22float2(hp[3]);
                rv[0] = f0.x; rv[1] = f0.y; rv[2] = f1.x; rv[3] = f1.y;
                rv[4] = f2.x; rv[5] = f2.y; rv[6] = f3.x; rv[7] = f3.y;
            }
            uint4 rw;
            float r0, r1;
            r0 = (rv[0] - mu[0]) * rs[0] + 1e-4f; r1 = (rv[1] - mu[1]) * rs[1] + 1e-4f;
            rw.x = (uint32_t)hfu(r0) | ((uint32_t)hfu(r1) << 16);
            r0 = (rv[2] - mu[2]) * rs[2] + 1e-4f; r1 = (rv[3] - mu[3]) * rs[3] + 1e-4f;
            rw.y = (uint32_t)hfu(r0) | ((uint32_t)hfu(r1) << 16);
            r0 = (rv[4] - mu[4]) * rs[4] + 1e-4f; r1 = (rv[5] - mu[5]) * rs[5] + 1e-4f;
            rw.z = (uint32_t)hfu(r0) | ((uint32_t)hfu(r1) << 16);
            r0 = (rv[6] - mu[6]) * rs[6] + 1e-4f; r1 = (rv[7] - mu[7]) * rs[7] + 1e-4f;
            rw.w = (uint32_t)hfu(r0) | ((uint32_t)hfu(r1) << 16);
            ((uint4*)g_hhi)[(size_t)node * 16 + fl] = rw;
        }
    }
}

// ---------------------------------------------------------------------------
// HMMA GEMM fp16 2-term (exact R11): 12 chunks of K=32 {A, B_hi, B_lo}
// (8KB tiles, SW64). Computes A*B_hi + A*B_lo. Epilogue: +bias, relu,
// +residual, fp16 output copy (next layer's gather source), BN stats.
// ---------------------------------------------------------------------------
#define T32B 8192                  // 128 rows x 64 bytes
#define CHUNKB (3 * T32B)          // A | Bh | Bl
#define SMEMB (2 * CHUNKB + 1024)

__global__ void __launch_bounds__(256, 2)
gemm_mma(const unsigned short* __restrict__ Wb, const float* __restrict__ bias,
         const float* __restrict__ res, float* __restrict__ out,
         unsigned short* __restrict__ outh, int do_stats) {
    extern __shared__ char smraw[];
    __shared__ float s_stats[256];
    uint32_t sb0 = smem_u32(smraw);
    const uint32_t sb = (sb0 + 1023u) & ~1023u;

    const int tid = threadIdx.x;
    const int wid = tid >> 5;
    const int lane = tid & 31;
    const int rowBase = blockIdx.x * 128;

    s_stats[tid] = 0.f;

    const int r = tid >> 1;
    const int jb = (tid & 1) * 2;
    const int gnode = min(rowBase + r, NN - 1);
    const unsigned short* brow = Wb + (size_t)r * KW;

    const int warpM = wid >> 2;
    const int warpN = wid & 3;

    float acc[4][4][4];
#pragma unroll
    for (int mi = 0; mi < 4; mi++)
#pragma unroll
        for (int ni = 0; ni < 4; ni++)
#pragma unroll
            for (int q = 0; q < 4; q++) acc[mi][ni][q] = 0.f;

    const int a_row = warpM * 64 + ((lane >> 3) & 1) * 8 + (lane & 7);
    const int a_k8 = (lane >> 4) * 8;
    const int b_row = warpN * 32 + ((lane >> 4) & 1) * 8 + (lane & 7);
    const int b_k8 = ((lane >> 3) & 1) * 8;

#define LOAD_CHUNK(c, buf) do { \
        const uint32_t base = sb + (buf) * CHUNKB; \
        const int kg = (c) * 32; \
        const unsigned short* a = (kg < 256) \
            ? g_mhi + (size_t)gnode * 256 + kg \
            : g_hhi + (size_t)gnode * 128 + (kg - 256); \
        const unsigned short* bh = brow + (c) * 32; \
        const unsigned short* bl = brow + 384 + (c) * 32; \
        _Pragma("unroll") \
        for (int i = 0; i < 2; i++) { \
            const int j = jb + i; \
            const uint32_t sw = SWZ64(r * 64 + j * 16); \
            CP_ASYNC16(base + sw,             a + j * 8); \
            CP_ASYNC16(base + T32B + sw,      bh + j * 8); \
            CP_ASYNC16(base + 2 * T32B + sw,  bl + j * 8); \
        } \
        CP_COMMIT(); \
    } while (0)

    LOAD_CHUNK(0, 0);

#pragma unroll 1
    for (int c = 0; c < NCH; c++) {
        CP_WAIT0();
        __syncthreads();
        if (c + 1 < NCH) LOAD_CHUNK(c + 1, (c + 1) & 1);

        const uint32_t aT = sb + (c & 1) * CHUNKB;
        const uint32_t bH = aT + T32B;
        const uint32_t bL = aT + 2 * T32B;
#pragma unroll
        for (int k16 = 0; k16 < 2; k16++) {
            uint32_t afr[4][4], bhf[4][2], blf[4][2];
#pragma unroll
            for (int mi = 0; mi < 4; mi++) {
                const uint32_t addr = aT +
                    SWZ64((a_row + mi * 16) * 64 + (k16 * 16 + a_k8) * 2);
                asm volatile("ldmatrix.sync.aligned.m8n8.x4.shared.b16 "
                             "{%0,%1,%2,%3}, [%4];"
                             : "=r"(afr[mi][0]), "=r"(afr[mi][1]),
                               "=r"(afr[mi][2]), "=r"(afr[mi][3])
                             : "r"(addr));
            }
#pragma unroll
            for (int p = 0; p < 2; p++) {
                const uint32_t addr = bH +
                    SWZ64((b_row + p * 16) * 64 + (k16 * 16 + b_k8) * 2);
                asm volatile("ldmatrix.sync.aligned.m8n8.x4.shared.b16 "
                             "{%0,%1,%2,%3}, [%4];"
                             : "=r"(bhf[2 * p][0]), "=r"(bhf[2 * p][1]),
                               "=r"(bhf[2 * p + 1][0]), "=r"(bhf[2 * p + 1][1])
                             : "r"(addr));
            }
#pragma unroll
            for (int mi = 0; mi < 4; mi++)
#pragma unroll
                for (int ni = 0; ni < 4; ni++) {
                    asm volatile(
                        "mma.sync.aligned.m16n8k16.row.col.f32.f16.f16.f32 "
                        "{%0,%1,%2,%3}, {%4,%5,%6,%7}, {%8,%9}, {%0,%1,%2,%3};"
                        : "+f"(acc[mi][ni][0]), "+f"(acc[mi][ni][1]),
                          "+f"(acc[mi][ni][2]), "+f"(acc[mi][ni][3])
                        : "r"(afr[mi][0]), "r"(afr[mi][1]),
                          "r"(afr[mi][2]), "r"(afr[mi][3]),
                          "r"(bhf[ni][0]), "r"(bhf[ni][1]));
                }
#pragma unroll
            for (int p = 0; p < 2; p++) {
                const uint32_t addr = bL +
                    SWZ64((b_row + p * 16) * 64 + (k16 * 16 + b_k8) * 2);
                asm volatile("ldmatrix.sync.aligned.m8n8.x4.shared.b16 "
                             "{%0,%1,%2,%3}, [%4];"
                             : "=r"(blf[2 * p][0]), "=r"(blf[2 * p][1]),
                               "=r"(blf[2 * p + 1][0]), "=r"(blf[2 * p + 1][1])
                             : "r"(addr));
            }
#pragma unroll
            for (int mi = 0; mi < 4; mi++)
#pragma unroll
                for (int ni = 0; ni < 4; ni++) {
                    asm volatile(
                        "mma.sync.aligned.m16n8k16.row.col.f32.f16.f16.f32 "
                        "{%0,%1,%2,%3}, {%4,%5,%6,%7}, {%8,%9}, {%0,%1,%2,%3};"
                        : "+f"(acc[mi][ni][0]), "+f"(acc[mi][ni][1]),
                          "+f"(acc[mi][ni][2]), "+f"(acc[mi][ni][3])
                        : "r"(afr[mi][0]), "r"(afr[mi][1]),
                          "r"(afr[mi][2]), "r"(afr[mi][3]),
                          "r"(blf[ni][0]), "r"(blf[ni][1]));
                }
        }
    }
#undef LOAD_CHUNK

    // ---- epilogue: +bias, relu, +residual, fp16 copy, stats ----
    const int mBase = rowBase + warpM * 64 + (lane >> 2);
    const int nBase = warpN * 32 + (lane & 3) * 2;
#pragma unroll
    for (int ni = 0; ni < 4; ni++) {
        const int n0 = nBase + ni * 8;
        const float2 bv = *(const float2*)(bias + n0);
        float cs0 = 0.f, cs1 = 0.f, cq0 = 0.f, cq1 = 0.f;
#pragma unroll
        for (int mi = 0; mi < 4; mi++) {
#pragma unroll
            for (int h = 0; h < 2; h++) {
                const int m = mBase + mi * 16 + h * 8;
                if (m < NN) {
                    float2 o;
                    o.x = fmaxf(acc[mi][ni][h * 2 + 0] + bv.x, 0.f);
                    o.y = fmaxf(acc[mi][ni][h * 2 + 1] + bv.y, 0.f);
                    if (res) {
                        const float2 rv = *(const float2*)(res + (size_t)m * NF + n0);
                        o.x += rv.x; o.y += rv.y;
                    }
                    *(float2*)(out + (size_t)m * NF + n0) = o;
                    if (outh) {
                        const __half2 hv = __floats2half2_rn(o.x, o.y);
                        *(__half2*)(outh + (size_t)m * NF + n0) = hv;
                    }
                    cs0 += o.x; cs1 += o.y;
                    cq0 += o.x * o.x; cq1 += o.y * o.y;
                }
            }
        }
        if (do_stats) {
#pragma unroll
            for (int off = 4; off < 32; off <<= 1) {
                cs0 += __shfl_xor_sync(0xffffffffu, cs0, off);
                cs1 += __shfl_xor_sync(0xffffffffu, cs1, off);
                cq0 += __shfl_xor_sync(0xffffffffu, cq0, off);
                cq1 += __shfl_xor_sync(0xffffffffu, cq1, off);
            }
            if ((lane >> 2) == 0) {
                atomicAdd(&s_stats[n0], cs0);
                atomicAdd(&s_stats[n0 + 1], cs1);
                atomicAdd(&s_stats[128 + n0], cq0);
                atomicAdd(&s_stats[128 + n0 + 1], cq1);
            }
        }
    }
    if (do_stats) {
        __syncthreads();
        atomicAdd(&g_stats[tid], s_stats[tid]);
    }
}

// ---------------------------------------------------------------------------
extern "C" void kernel_launch(void* const* d_in, const int* in_sizes, int n_in,
                              void* d_out, int out_size) {
    const float* x = (const float*)d_in[0];
    const int* ei = (const int*)d_in[1];
    const int* et = (const int*)d_in[2];
    const float* W0rel = (const float*)d_in[3];
    const float* W0root = (const float*)d_in[4];
    const float* b0 = (const float*)d_in[5];
    const float* Wsrel = (const float*)d_in[6];
    const float* Wsroot = (const float*)d_in[7];
    const float* bs = (const float*)d_in[8];
    float* outp = (float*)d_out;

    const int* src = ei;
    const int* dst = ei + NE;

    void *p_stats = 0, *p_h = 0, *p_deg = 0, *p_wb = 0, *p_inh = 0;
    cudaGetSymbolAddress(&p_stats, g_stats);
    cudaGetSymbolAddress(&p_h, g_h);
    cudaGetSymbolAddress(&p_deg, g_deg);
    cudaGetSymbolAddress(&p_wb, g_wb);
    cudaGetSymbolAddress(&p_inh, g_inh);

    static int smem_set = 0;
    if (!smem_set) {
        cudaFuncSetAttribute(gemm_mma, cudaFuncAttributeMaxDynamicSharedMemorySize, SMEMB);
        smem_set = 1;
    }

    // ---- CSR build + weight prep (once per launch) ----
    cudaMemsetAsync(p_deg, 0, NSEG * sizeof(int));
    hist_kernel<<<(NE + 255) / 256, 256>>>(dst, et);
    scan1_kernel<<<SCAN_BLKS, 256>>>();
    scan2_kernel<<<1, 128>>>();
    addoff_kernel<<<(NSEG + 255) / 256, 256>>>();
    fill_kernel<<<(NE + 255) / 256, 256>>>(src, dst, et);
    wt_kernel<<<(4 * NF * KW + 255) / 256, 256>>>(W0rel, W0root, Wsrel, Wsroot);

    // layer-0 input stats + fp16 copy
    cudaMemsetAsync(p_stats, 0, 2 * NF * sizeof(float));
    stats_kernel<<<256, 256>>>(x);
    conv16_kernel<<<(NN * NF / 4 + 255) / 256, 256>>>(x);

    // ---- layers ----
    for (int c = 0; c < 4; c++) {
        const float* bb = (c == 0) ? b0 : bs + (c - 1) * NF;
        const float* res = (c == 0) ? (const float*)0 : (const float*)p_h;
        float* o = (c == 3) ? outp : (float*)p_h;
        unsigned short* oh = (c < 3) ? (unsigned short*)p_inh : (unsigned short*)0;
        const unsigned short* wb = (const unsigned short*)p_wb + (size_t)c * NF * KW;
        const int do_stats = (c < 3) ? 1 : 0;

        agg_kernel<<<(NSEG * 32 + 255) / 256, 256>>>();
        if (do_stats) cudaMemsetAsync(p_stats, 0, 2 * NF * sizeof(float));
        gemm_mma<<<(NN + 127) / 128, 256, SMEMB>>>(wb, bb, res, o, oh, do_stats);
    }
}

// round 16
// speedup vs baseline: 1.2631x; 1.2631x over previous
#include <cuda_runtime.h>
#include <cuda_fp16.h>
#include <cstdint>

#define NN 50000
#define NF 128
#define NE 600000
#define NR 2
#define NSEG (NN * NR)          // 100000
#define SCAN_BLKS 98            // ceil(NSEG / 1024)
#define KW 768                  // weight buffer K: [hi 384 | lo 384] fp16
#define NCH 12                  // 12 chunks of K=32

// ---------------- scratch (device globals; no allocation allowed) ----------
__device__ float g_h[(size_t)NN * NF];
__device__ float g_stats[4][2 * NF];   // per-layer BN stat buffers
__device__ int   g_deg[NSEG];
__device__ int   g_cursor[NSEG];
__device__ float g_icnt[NSEG];
__device__ int   g_csr[NE];
__device__ int   g_bsum[128];
// fp16 operands (A side: hi only; B side: hi+lo)
__device__ unsigned short g_hhi[(size_t)NN * NF];
__device__ unsigned short g_mhi[(size_t)NN * NR * NF];
__device__ unsigned short g_wb[(size_t)4 * NF * KW];   // [layer][n=128][hi384|lo384]

// ---------------- helpers ---------------------------------------------------
__device__ __forceinline__ uint32_t smem_u32(const void* p) {
    uint32_t a;
    asm("{ .reg .u64 t; cvta.to.shared.u64 t, %1; cvt.u32.u64 %0, t; }"
        : "=r"(a) : "l"(p));
    return a;
}
#define SWZ64(off) ((off) ^ (((off) >> 3) & 0x30))
#define CP_ASYNC16(sm, gp) \
    asm volatile("cp.async.cg.shared.global [%0], [%1], 16;" :: "r"(sm), "l"(gp) : "memory")
#define CP_COMMIT() asm volatile("cp.async.commit_group;" ::: "memory")
#define CP_WAIT0()  asm volatile("cp.async.wait_group 0;" ::: "memory")

static __device__ __forceinline__ unsigned short hfu(float f) {
    __half h = __float2half_rn(f);
    return *(unsigned short*)&h;
}
static __device__ __forceinline__ float hff(unsigned short u) {
    __half h = *(__half*)&u;
    return __half2float(h);
}
static __device__ __forceinline__ uint2 pack4h(float4 v) {
    uint2 o;
    o.x = (uint32_t)hfu(v.x) | ((uint32_t)hfu(v.y) << 16);
    o.y = (uint32_t)hfu(v.z) | ((uint32_t)hfu(v.w) << 16);
    return o;
}

// ---------------------------------------------------------------------------
// CSR build (once per launch)
// ---------------------------------------------------------------------------
__global__ void hist_kernel(const int* __restrict__ dst, const int* __restrict__ et) {
    const int e = blockIdx.x * blockDim.x + threadIdx.x;
    if (e >= NE) return;
    atomicAdd(&g_deg[dst[e] * NR + et[e]], 1);
}
__global__ void scan1_kernel() {
    __shared__ int sh[256];
    const int t = threadIdx.x;
    const int base = blockIdx.x * 1024 + t * 4;
    int v[4];
#pragma unroll
    for (int k = 0; k < 4; k++) v[k] = (base + k < NSEG) ? g_deg[base + k] : 0;
    int sum = v[0] + v[1] + v[2] + v[3];
    sh[t] = sum;
    __syncthreads();
#pragma unroll
    for (int off = 1; off < 256; off <<= 1) {
        int add = (t >= off) ? sh[t - off] : 0;
        __syncthreads();
        sh[t] += add;
        __syncthreads();
    }
    int ex = sh[t] - sum;
#pragma unroll
    for (int k = 0; k < 4; k++) {
        if (base + k < NSEG) g_cursor[base + k] = ex;
        ex += v[k];
    }
    if (t == 255) g_bsum[blockIdx.x] = sh[255];
}
__global__ void scan2_kernel() {
    __shared__ int sh[128];
    const int t = threadIdx.x;
    int v = (t < SCAN_BLKS) ? g_bsum[t] : 0;
    sh[t] = v;
    __syncthreads();
#pragma unroll
    for (int off = 1; off < 128; off <<= 1) {
        int add = (t >= off) ? sh[t - off] : 0;
        __syncthreads();
        sh[t] += add;
        __syncthreads();
    }
    if (t < SCAN_BLKS) g_bsum[t] = sh[t] - v;   // exclusive
}
__global__ void addoff_kernel() {
    const int i = blockIdx.x * blockDim.x + threadIdx.x;
    if (i >= NSEG) return;
    g_cursor[i] += g_bsum[i >> 10];
    g_icnt[i] = 1.0f / (float)max(g_deg[i], 1);
}
__global__ void fill_kernel(const int* __restrict__ src, const int* __restrict__ dst,
                            const int* __restrict__ et) {
    const int e = blockIdx.x * blockDim.x + threadIdx.x;
    if (e >= NE) return;
    const int pos = atomicAdd(&g_cursor[dst[e] * NR + et[e]], 1);
    g_csr[pos] = src[e];
}

// ---------------------------------------------------------------------------
// Weight prep (all 4 layers): g_wb[l][n][k<384: fp16hi(W); k>=384: fp16lo]
// ---------------------------------------------------------------------------
__global__ void wt_kernel(const float* __restrict__ W0rel, const float* __restrict__ W0root,
                          const float* __restrict__ Wsrel, const float* __restrict__ Wsroot) {
    const int gi = blockIdx.x * blockDim.x + threadIdx.x;
    if (gi >= 4 * NF * KW) return;
    const int l = gi / (NF * KW);
    const int i = gi % (NF * KW);
    const int n = i / KW;
    const int kp = i % KW;
    const int k = (kp < 384) ? kp : (kp - 384);
    const float* Wrel = (l == 0) ? W0rel : Wsrel + (size_t)(l - 1) * NR * NF * NF;
    const float* Wroot = (l == 0) ? W0root : Wsroot + (size_t)(l - 1) * NF * NF;
    const float w = (k < 256) ? Wrel[k * NF + n] : Wroot[(k - 256) * NF + n];
    const unsigned short hi = hfu(w);
    g_wb[gi] = (kp < 384) ? hi : hfu(w - hff(hi));
}

// ---------------------------------------------------------------------------
// Column stats for layer 0 input -> g_stats[0]
// ---------------------------------------------------------------------------
__global__ void stats_kernel(const float* __restrict__ in) {
    __shared__ float ss[256], sq[256];
    const int tid = threadIdx.x;
    const int f = tid & 127;
    const int half = tid >> 7;
    float s = 0.f, s2 = 0.f;
    for (int r = blockIdx.x * 2 + half; r < NN; r += gridDim.x * 2) {
        float v = in[r * NF + f];
        s += v; s2 += v * v;
    }
    ss[tid] = s; sq[tid] = s2;
    __syncthreads();
    if (tid < 128) {
        atomicAdd(&g_stats[0][f], ss[tid] + ss[tid + 128]);
        atomicAdd(&g_stats[0][NF + f], sq[tid] + sq[tid + 128]);
    }
}

// ---------------------------------------------------------------------------
// Fused aggregation + BN: warp per (node, relation) segment on RAW fp32 input.
// Stats from g_stats[layer]. Writes fp16 mean (A operand). rel==0 warps also
// write BN(own row) fp16 root operand.
// ---------------------------------------------------------------------------
__global__ void agg_kernel(const float* __restrict__ in, int layer) {
    const int seg = (blockIdx.x * blockDim.x + threadIdx.x) >> 5;
    const int lane = threadIdx.x & 31;
    if (seg >= NSEG) return;
    const int end = g_cursor[seg];
    const int deg = g_deg[seg];
    const int start = end - deg;
    float4 acc = make_float4(0.f, 0.f, 0.f, 0.f);
    const float4* in4 = (const float4*)in;
    for (int base = start; base < end; base += 32) {
        const int nrem = end - base;
        const int cnt = (nrem < 32) ? nrem : 32;
        const int myid = (lane < cnt) ? __ldg(&g_csr[base + lane]) : 0;
        int e = 0;
        for (; e + 4 <= cnt; e += 4) {
            const int s0 = __shfl_sync(0xffffffffu, myid, e + 0);
            const int s1 = __shfl_sync(0xffffffffu, myid, e + 1);
            const int s2 = __shfl_sync(0xffffffffu, myid, e + 2);
            const int s3 = __shfl_sync(0xffffffffu, myid, e + 3);
            const float4 v0 = in4[(size_t)s0 * 32 + lane];
            const float4 v1 = in4[(size_t)s1 * 32 + lane];
            const float4 v2 = in4[(size_t)s2 * 32 + lane];
            const float4 v3 = in4[(size_t)s3 * 32 + lane];
            acc.x += v0.x + v1.x + v2.x + v3.x;
            acc.y += v0.y + v1.y + v2.y + v3.y;
            acc.z += v0.z + v1.z + v2.z + v3.z;
            acc.w += v0.w + v1.w + v2.w + v3.w;
        }
        for (; e < cnt; e++) {
            const int s = __shfl_sync(0xffffffffu, myid, e);
            const float4 v = in4[(size_t)s * 32 + lane];
            acc.x += v.x; acc.y += v.y; acc.z += v.z; acc.w += v.w;
        }
    }
    const float ic = g_icnt[seg];
    const float live = (deg > 0) ? 1.0f : 0.0f;
    const int f = lane * 4;
    const float invn = 1.0f / NN;
    const float* stats = g_stats[layer];
    const float4 st = *(const float4*)(stats + f);
    const float4 sq = *(const float4*)(stats + NF + f);
    float mux, muy, muz, muw, rsx, rsy, rsz, rsw;
    mux = st.x * invn; rsx = rsqrtf(sq.x * invn - mux * mux + 1e-5f);
    muy = st.y * invn; rsy = rsqrtf(sq.y * invn - muy * muy + 1e-5f);
    muz = st.z * invn; rsz = rsqrtf(sq.z * invn - muz * muz + 1e-5f);
    muw = st.w * invn; rsw = rsqrtf(sq.w * invn - muw * muw + 1e-5f);

    float4 o;
    o.x = live * ((acc.x * ic - mux) * rsx + 1e-4f);
    o.y = live * ((acc.y * ic - muy) * rsy + 1e-4f);
    o.z = live * ((acc.z * ic - muz) * rsz + 1e-4f);
    o.w = live * ((acc.w * ic - muw) * rsw + 1e-4f);
    ((uint2*)g_mhi)[(size_t)seg * 32 + lane] = pack4h(o);

    if ((seg & 1) == 0) {
        const int node = seg >> 1;
        const float4 v = in4[(size_t)node * 32 + lane];
        float4 r;
        r.x = (v.x - mux) * rsx + 1e-4f;
        r.y = (v.y - muy) * rsy + 1e-4f;
        r.z = (v.z - muz) * rsz + 1e-4f;
        r.w = (v.w - muw) * rsw + 1e-4f;
        ((uint2*)g_hhi)[(size_t)node * 32 + lane] = pack4h(r);
    }
}

// ---------------------------------------------------------------------------
// HMMA GEMM fp16 2-term (R11): 12 chunks of K=32 {A, B_hi, B_lo}
// (8KB tiles, SW64). Epilogue: +bias, relu, +residual,
// next-layer BN stats into g_stats[layer+1] (pre-zeroed upfront).
// ---------------------------------------------------------------------------
#define T32B 8192                  // 128 rows x 64 bytes
#define CHUNKB (3 * T32B)          // A | Bh | Bl
#define SMEMB (2 * CHUNKB + 1024)

__global__ void __launch_bounds__(256, 2)
gemm_mma(const unsigned short* __restrict__ Wb, const float* __restrict__ bias,
         const float* __restrict__ res, float* __restrict__ out, int layer) {
    extern __shared__ char smraw[];
    __shared__ float s_stats[256];
    uint32_t sb0 = smem_u32(smraw);
    const uint32_t sb = (sb0 + 1023u) & ~1023u;

    const int tid = threadIdx.x;
    const int wid = tid >> 5;
    const int lane = tid & 31;
    const int rowBase = blockIdx.x * 128;
    const int do_stats = (layer < 3);

    s_stats[tid] = 0.f;

    const int r = tid >> 1;
    const int jb = (tid & 1) * 2;
    const int gnode = min(rowBase + r, NN - 1);
    const unsigned short* brow = Wb + (size_t)r * KW;

    const int warpM = wid >> 2;
    const int warpN = wid & 3;

    float acc[4][4][4];
#pragma unroll
    for (int mi = 0; mi < 4; mi++)
#pragma unroll
        for (int ni = 0; ni < 4; ni++)
#pragma unroll
            for (int q = 0; q < 4; q++) acc[mi][ni][q] = 0.f;

    const int a_row = warpM * 64 + ((lane >> 3) & 1) * 8 + (lane & 7);
    const int a_k8 = (lane >> 4) * 8;
    const int b_row = warpN * 32 + ((lane >> 4) & 1) * 8 + (lane & 7);
    const int b_k8 = ((lane >> 3) & 1) * 8;

#define LOAD_CHUNK(c, buf) do { \
        const uint32_t base = sb + (buf) * CHUNKB; \
        const int kg = (c) * 32; \
        const unsigned short* a = (kg < 256) \
            ? g_mhi + (size_t)gnode * 256 + kg \
            : g_hhi + (size_t)gnode * 128 + (kg - 256); \
        const unsigned short* bh = brow + (c) * 32; \
        const unsigned short* bl = brow + 384 + (c) * 32; \
        _Pragma("unroll") \
        for (int i = 0; i < 2; i++) { \
            const int j = jb + i; \
            const uint32_t sw = SWZ64(r * 64 + j * 16); \
            CP_ASYNC16(base + sw,             a + j * 8); \
            CP_ASYNC16(base + T32B + sw,      bh + j * 8); \
            CP_ASYNC16(base + 2 * T32B + sw,  bl + j * 8); \
        } \
        CP_COMMIT(); \
    } while (0)

    LOAD_CHUNK(0, 0);

#pragma unroll 1
    for (int c = 0; c < NCH; c++) {
        CP_WAIT0();
        __syncthreads();
        if (c + 1 < NCH) LOAD_CHUNK(c + 1, (c + 1) & 1);

        const uint32_t aT = sb + (c & 1) * CHUNKB;
        const uint32_t bH = aT + T32B;
        const uint32_t bL = aT + 2 * T32B;
#pragma unroll
        for (int k16 = 0; k16 < 2; k16++) {
            uint32_t afr[4][4], bhf[4][2], blf[4][2];
#pragma unroll
            for (int mi = 0; mi < 4; mi++) {
                const uint32_t addr = aT +
                    SWZ64((a_row + mi * 16) * 64 + (k16 * 16 + a_k8) * 2);
                asm volatile("ldmatrix.sync.aligned.m8n8.x4.shared.b16 "
                             "{%0,%1,%2,%3}, [%4];"
                             : "=r"(afr[mi][0]), "=r"(afr[mi][1]),
                               "=r"(afr[mi][2]), "=r"(afr[mi][3])
                             : "r"(addr));
            }
#pragma unroll
            for (int p = 0; p < 2; p++) {
                const uint32_t addr = bH +
                    SWZ64((b_row + p * 16) * 64 + (k16 * 16 + b_k8) * 2);
                asm volatile("ldmatrix.sync.aligned.m8n8.x4.shared.b16 "
                             "{%0,%1,%2,%3}, [%4];"
                             : "=r"(bhf[2 * p][0]), "=r"(bhf[2 * p][1]),
                               "=r"(bhf[2 * p + 1][0]), "=r"(bhf[2 * p + 1][1])
                             : "r"(addr));
            }
#pragma unroll
            for (int mi = 0; mi < 4; mi++)
#pragma unroll
                for (int ni = 0; ni < 4; ni++) {
                    asm volatile(
                        "mma.sync.aligned.m16n8k16.row.col.f32.f16.f16.f32 "
                        "{%0,%1,%2,%3}, {%4,%5,%6,%7}, {%8,%9}, {%0,%1,%2,%3};"
                        : "+f"(acc[mi][ni][0]), "+f"(acc[mi][ni][1]),
                          "+f"(acc[mi][ni][2]), "+f"(acc[mi][ni][3])
                        : "r"(afr[mi][0]), "r"(afr[mi][1]),
                          "r"(afr[mi][2]), "r"(afr[mi][3]),
                          "r"(bhf[ni][0]), "r"(bhf[ni][1]));
                }
#pragma unroll
            for (int p = 0; p < 2; p++) {
                const uint32_t addr = bL +
                    SWZ64((b_row + p * 16) * 64 + (k16 * 16 + b_k8) * 2);
                asm volatile("ldmatrix.sync.aligned.m8n8.x4.shared.b16 "
                             "{%0,%1,%2,%3}, [%4];"
                             : "=r"(blf[2 * p][0]), "=r"(blf[2 * p][1]),
                               "=r"(blf[2 * p + 1][0]), "=r"(blf[2 * p + 1][1])
                             : "r"(addr));
            }
#pragma unroll
            for (int mi = 0; mi < 4; mi++)
#pragma unroll
                for (int ni = 0; ni < 4; ni++) {
                    asm volatile(
                        "mma.sync.aligned.m16n8k16.row.col.f32.f16.f16.f32 "
                        "{%0,%1,%2,%3}, {%4,%5,%6,%7}, {%8,%9}, {%0,%1,%2,%3};"
                        : "+f"(acc[mi][ni][0]), "+f"(acc[mi][ni][1]),
                          "+f"(acc[mi][ni][2]), "+f"(acc[mi][ni][3])
                        : "r"(afr[mi][0]), "r"(afr[mi][1]),
                          "r"(afr[mi][2]), "r"(afr[mi][3]),
                          "r"(blf[ni][0]), "r"(blf[ni][1]));
                }
        }
    }
#undef LOAD_CHUNK

    // ---- epilogue: +bias, relu, +residual, stats ----
    const int mBase = rowBase + warpM * 64 + (lane >> 2);
    const int nBase = warpN * 32 + (lane & 3) * 2;
#pragma unroll
    for (int ni = 0; ni < 4; ni++) {
        const int n0 = nBase + ni * 8;
        const float2 bv = *(const float2*)(bias + n0);
        float cs0 = 0.f, cs1 = 0.f, cq0 = 0.f, cq1 = 0.f;
#pragma unroll
        for (int mi = 0; mi < 4; mi++) {
#pragma unroll
            for (int h = 0; h < 2; h++) {
                const int m = mBase + mi * 16 + h * 8;
                if (m < NN) {
                    float2 o;
                    o.x = fmaxf(acc[mi][ni][h * 2 + 0] + bv.x, 0.f);
                    o.y = fmaxf(acc[mi][ni][h * 2 + 1] + bv.y, 0.f);
                    if (res) {
                        const float2 rv = *(const float2*)(res + (size_t)m * NF + n0);
                        o.x += rv.x; o.y += rv.y;
                    }
                    *(float2*)(out + (size_t)m * NF + n0) = o;
                    cs0 += o.x; cs1 += o.y;
                    cq0 += o.x * o.x; cq1 += o.y * o.y;
                }
            }
        }
        if (do_stats) {
#pragma unroll
            for (int off = 4; off < 32; off <<= 1) {
                cs0 += __shfl_xor_sync(0xffffffffu, cs0, off);
                cs1 += __shfl_xor_sync(0xffffffffu, cs1, off);
                cq0 += __shfl_xor_sync(0xffffffffu, cq0, off);
                cq1 += __shfl_xor_sync(0xffffffffu, cq1, off);
            }
            if ((lane >> 2) == 0) {
                atomicAdd(&s_stats[n0], cs0);
                atomicAdd(&s_stats[n0 + 1], cs1);
                atomicAdd(&s_stats[128 + n0], cq0);
                atomicAdd(&s_stats[128 + n0 + 1], cq1);
            }
        }
    }
    if (do_stats) {
        __syncthreads();
        atomicAdd(&g_stats[layer + 1][tid], s_stats[tid]);
    }
}

// ---------------------------------------------------------------------------
extern "C" void kernel_launch(void* const* d_in, const int* in_sizes, int n_in,
                              void* d_out, int out_size) {
    const float* x = (const float*)d_in[0];
    const int* ei = (const int*)d_in[1];
    const int* et = (const int*)d_in[2];
    const float* W0rel = (const float*)d_in[3];
    const float* W0root = (const float*)d_in[4];
    const float* b0 = (const float*)d_in[5];
    const float* Wsrel = (const float*)d_in[6];
    const float* Wsroot = (const float*)d_in[7];
    const float* bs = (const float*)d_in[8];
    float* outp = (float*)d_out;

    const int* src = ei;
    const int* dst = ei + NE;

    void *p_stats = 0, *p_h = 0, *p_deg = 0, *p_wb = 0;
    cudaGetSymbolAddress(&p_stats, g_stats);
    cudaGetSymbolAddress(&p_h, g_h);
    cudaGetSymbolAddress(&p_deg, g_deg);
    cudaGetSymbolAddress(&p_wb, g_wb);

    static int smem_set = 0;
    if (!smem_set) {
        cudaFuncSetAttribute(gemm_mma, cudaFuncAttributeMaxDynamicSharedMemorySize, SMEMB);
        smem_set = 1;
    }

    // ---- CSR build + weight prep (once per launch) ----
    cudaMemsetAsync(p_deg, 0, NSEG * sizeof(int));
    cudaMemsetAsync(p_stats, 0, 4 * 2 * NF * sizeof(float));   // all stat buffers
    hist_kernel<<<(NE + 255) / 256, 256>>>(dst, et);
    scan1_kernel<<<SCAN_BLKS, 256>>>();
    scan2_kernel<<<1, 128>>>();
    addoff_kernel<<<(NSEG + 255) / 256, 256>>>();
    fill_kernel<<<(NE + 255) / 256, 256>>>(src, dst, et);
    wt_kernel<<<(4 * NF * KW + 255) / 256, 256>>>(W0rel, W0root, Wsrel, Wsroot);

    // layer-0 input stats -> g_stats[0]
    stats_kernel<<<256, 256>>>(x);

    // ---- layers ----
    for (int c = 0; c < 4; c++) {
        const float* in = (c == 0) ? x : (const float*)p_h;
        const float* bb = (c == 0) ? b0 : bs + (c - 1) * NF;
        const float* res = (c == 0) ? (const float*)0 : (const float*)p_h;
        float* o = (c == 3) ? outp : (float*)p_h;
        const unsigned short* wb = (const unsigned short*)p_wb + (size_t)c * NF * KW;

        agg_kernel<<<(NSEG * 32 + 255) / 256, 256>>>(in, c);
        gemm_mma<<<(NN + 127) / 128, 256, SMEMB>>>(wb, bb, res, o, c);
    }
}

// round 17
// speedup vs baseline: 1.4141x; 1.1195x over previous
#include <cuda_runtime.h>
#include <cuda_fp16.h>
#include <cstdint>

#define NN 50000
#define NF 128
#define NE 600000
#define NR 2
#define NSEG (NN * NR)          // 100000
#define SCAN_BLKS 98            // ceil(NSEG / 1024)
#define KW 768                  // weight buffer K: [hi 384 | lo 384] fp16
#define NCH 12                  // 12 chunks of K=32
// prologue block partitions
#define HB ((NE + 255) / 256)           // 2344 hist blocks
#define WB ((4 * NF * KW) / 256)        // 1536 wt blocks
#define SB 256                          // stats blocks
#define PRO_BLKS (HB + WB + SB)

// ---------------- scratch (device globals; no allocation allowed) ----------
__device__ float g_h[(size_t)NN * NF];
__device__ float g_stats[4][2 * NF];   // per-layer BN stat buffers
__device__ int   g_deg[NSEG];
__device__ int   g_cursor[NSEG];
__device__ float g_icnt[NSEG];
__device__ int   g_csr[NE];
__device__ int   g_bsum[128];
// fp16 operands (A side: hi only; B side: hi+lo)
__device__ unsigned short g_hhi[(size_t)NN * NF];
__device__ unsigned short g_mhi[(size_t)NN * NR * NF];
__device__ unsigned short g_wb[(size_t)4 * NF * KW];   // [layer][n=128][hi384|lo384]

// ---------------- helpers ---------------------------------------------------
__device__ __forceinline__ uint32_t smem_u32(const void* p) {
    uint32_t a;
    asm("{ .reg .u64 t; cvta.to.shared.u64 t, %1; cvt.u32.u64 %0, t; }"
        : "=r"(a) : "l"(p));
    return a;
}
#define SWZ64(off) ((off) ^ (((off) >> 3) & 0x30))
#define CP_ASYNC16(sm, gp) \
    asm volatile("cp.async.cg.shared.global [%0], [%1], 16;" :: "r"(sm), "l"(gp) : "memory")
#define CP_COMMIT() asm volatile("cp.async.commit_group;" ::: "memory")
#define CP_WAIT0()  asm volatile("cp.async.wait_group 0;" ::: "memory")

static __device__ __forceinline__ unsigned short hfu(float f) {
    __half h = __float2half_rn(f);
    return *(unsigned short*)&h;
}
static __device__ __forceinline__ float hff(unsigned short u) {
    __half h = *(__half*)&u;
    return __half2float(h);
}
static __device__ __forceinline__ uint2 pack4h(float4 v) {
    uint2 o;
    o.x = (uint32_t)hfu(v.x) | ((uint32_t)hfu(v.y) << 16);
    o.y = (uint32_t)hfu(v.z) | ((uint32_t)hfu(v.w) << 16);
    return o;
}

// ---------------------------------------------------------------------------
// Fused prologue: hist (CSR histogram) + wt (weight split) + stats (layer-0 BN)
// Independent work items packed into one grid; overlap across SMs.
// ---------------------------------------------------------------------------
__global__ void prologue_kernel(const int* __restrict__ dst, const int* __restrict__ et,
                                const float* __restrict__ W0rel, const float* __restrict__ W0root,
                                const float* __restrict__ Wsrel, const float* __restrict__ Wsroot,
                                const float* __restrict__ x) {
    const int b = blockIdx.x;
    const int tid = threadIdx.x;
    if (b < HB) {
        // ---- histogram ----
        const int e = b * 256 + tid;
        if (e < NE) atomicAdd(&g_deg[dst[e] * NR + et[e]], 1);
    } else if (b < HB + WB) {
        // ---- weight split ----
        const int gi = (b - HB) * 256 + tid;
        const int l = gi / (NF * KW);
        const int i = gi % (NF * KW);
        const int n = i / KW;
        const int kp = i % KW;
        const int k = (kp < 384) ? kp : (kp - 384);
        const float* Wrel = (l == 0) ? W0rel : Wsrel + (size_t)(l - 1) * NR * NF * NF;
        const float* Wroot = (l == 0) ? W0root : Wsroot + (size_t)(l - 1) * NF * NF;
        const float w = (k < 256) ? Wrel[k * NF + n] : Wroot[(k - 256) * NF + n];
        const unsigned short hi = hfu(w);
        g_wb[gi] = (kp < 384) ? hi : hfu(w - hff(hi));
    } else {
        // ---- layer-0 column stats ----
        __shared__ float ss[256], sq[256];
        const int sb = b - HB - WB;      // 0..255
        const int f = tid & 127;
        const int half = tid >> 7;
        float s = 0.f, s2 = 0.f;
        for (int r = sb * 2 + half; r < NN; r += SB * 2) {
            float v = x[r * NF + f];
            s += v; s2 += v * v;
        }
        ss[tid] = s; sq[tid] = s2;
        __syncthreads();
        if (tid < 128) {
            atomicAdd(&g_stats[0][f], ss[tid] + ss[tid + 128]);
            atomicAdd(&g_stats[0][NF + f], sq[tid] + sq[tid + 128]);
        }
    }
}

// ---------------------------------------------------------------------------
// CSR build tail
// ---------------------------------------------------------------------------
__global__ void scan1_kernel() {
    __shared__ int sh[256];
    const int t = threadIdx.x;
    const int base = blockIdx.x * 1024 + t * 4;
    int v[4];
#pragma unroll
    for (int k = 0; k < 4; k++) v[k] = (base + k < NSEG) ? g_deg[base + k] : 0;
    int sum = v[0] + v[1] + v[2] + v[3];
    sh[t] = sum;
    __syncthreads();
#pragma unroll
    for (int off = 1; off < 256; off <<= 1) {
        int add = (t >= off) ? sh[t - off] : 0;
        __syncthreads();
        sh[t] += add;
        __syncthreads();
    }
    int ex = sh[t] - sum;
#pragma unroll
    for (int k = 0; k < 4; k++) {
        if (base + k < NSEG) g_cursor[base + k] = ex;
        ex += v[k];
    }
    if (t == 255) g_bsum[blockIdx.x] = sh[255];
}
__global__ void scan2_kernel() {
    __shared__ int sh[128];
    const int t = threadIdx.x;
    int v = (t < SCAN_BLKS) ? g_bsum[t] : 0;
    sh[t] = v;
    __syncthreads();
#pragma unroll
    for (int off = 1; off < 128; off <<= 1) {
        int add = (t >= off) ? sh[t - off] : 0;
        __syncthreads();
        sh[t] += add;
        __syncthreads();
    }
    if (t < SCAN_BLKS) g_bsum[t] = sh[t] - v;   // exclusive
}
__global__ void addoff_kernel() {
    const int i = blockIdx.x * blockDim.x + threadIdx.x;
    if (i >= NSEG) return;
    g_cursor[i] += g_bsum[i >> 10];
    g_icnt[i] = 1.0f / (float)max(g_deg[i], 1);
}
__global__ void fill_kernel(const int* __restrict__ src, const int* __restrict__ dst,
                            const int* __restrict__ et) {
    const int e = blockIdx.x * blockDim.x + threadIdx.x;
    if (e >= NE) return;
    const int pos = atomicAdd(&g_cursor[dst[e] * NR + et[e]], 1);
    g_csr[pos] = src[e];
}

// ---------------------------------------------------------------------------
// Fused aggregation + BN: warp per (node, relation) segment on RAW fp32 input.
// Stats from g_stats[layer]. Writes fp16 mean (A operand). rel==0 warps also
// write BN(own row) fp16 root operand.
// ---------------------------------------------------------------------------
__global__ void agg_kernel(const float* __restrict__ in, int layer) {
    const int seg = (blockIdx.x * blockDim.x + threadIdx.x) >> 5;
    const int lane = threadIdx.x & 31;
    if (seg >= NSEG) return;
    const int end = g_cursor[seg];
    const int deg = g_deg[seg];
    const int start = end - deg;
    float4 acc = make_float4(0.f, 0.f, 0.f, 0.f);
    const float4* in4 = (const float4*)in;
    for (int base = start; base < end; base += 32) {
        const int nrem = end - base;
        const int cnt = (nrem < 32) ? nrem : 32;
        const int myid = (lane < cnt) ? __ldg(&g_csr[base + lane]) : 0;
        int e = 0;
        for (; e + 4 <= cnt; e += 4) {
            const int s0 = __shfl_sync(0xffffffffu, myid, e + 0);
            const int s1 = __shfl_sync(0xffffffffu, myid, e + 1);
            const int s2 = __shfl_sync(0xffffffffu, myid, e + 2);
            const int s3 = __shfl_sync(0xffffffffu, myid, e + 3);
            const float4 v0 = in4[(size_t)s0 * 32 + lane];
            const float4 v1 = in4[(size_t)s1 * 32 + lane];
            const float4 v2 = in4[(size_t)s2 * 32 + lane];
            const float4 v3 = in4[(size_t)s3 * 32 + lane];
            acc.x += v0.x + v1.x + v2.x + v3.x;
            acc.y += v0.y + v1.y + v2.y + v3.y;
            acc.z += v0.z + v1.z + v2.z + v3.z;
            acc.w += v0.w + v1.w + v2.w + v3.w;
        }
        for (; e < cnt; e++) {
            const int s = __shfl_sync(0xffffffffu, myid, e);
            const float4 v = in4[(size_t)s * 32 + lane];
            acc.x += v.x; acc.y += v.y; acc.z += v.z; acc.w += v.w;
        }
    }
    const float ic = g_icnt[seg];
    const float live = (deg > 0) ? 1.0f : 0.0f;
    const int f = lane * 4;
    const float invn = 1.0f / NN;
    const float* stats = g_stats[layer];
    const float4 st = *(const float4*)(stats + f);
    const float4 sq = *(const float4*)(stats + NF + f);
    float mux, muy, muz, muw, rsx, rsy, rsz, rsw;
    mux = st.x * invn; rsx = rsqrtf(sq.x * invn - mux * mux + 1e-5f);
    muy = st.y * invn; rsy = rsqrtf(sq.y * invn - muy * muy + 1e-5f);
    muz = st.z * invn; rsz = rsqrtf(sq.z * invn - muz * muz + 1e-5f);
    muw = st.w * invn; rsw = rsqrtf(sq.w * invn - muw * muw + 1e-5f);

    float4 o;
    o.x = live * ((acc.x * ic - mux) * rsx + 1e-4f);
    o.y = live * ((acc.y * ic - muy) * rsy + 1e-4f);
    o.z = live * ((acc.z * ic - muz) * rsz + 1e-4f);
    o.w = live * ((acc.w * ic - muw) * rsw + 1e-4f);
    ((uint2*)g_mhi)[(size_t)seg * 32 + lane] = pack4h(o);

    if ((seg & 1) == 0) {
        const int node = seg >> 1;
        const float4 v = in4[(size_t)node * 32 + lane];
        float4 r;
        r.x = (v.x - mux) * rsx + 1e-4f;
        r.y = (v.y - muy) * rsy + 1e-4f;
        r.z = (v.z - muz) * rsz + 1e-4f;
        r.w = (v.w - muw) * rsw + 1e-4f;
        ((uint2*)g_hhi)[(size_t)node * 32 + lane] = pack4h(r);
    }
}

// ---------------------------------------------------------------------------
// HMMA GEMM fp16 2-term (R11): 12 chunks of K=32 {A, B_hi, B_lo}
// (8KB tiles, SW64). Epilogue: +bias, relu, +residual,
// next-layer BN stats into g_stats[layer+1] (pre-zeroed upfront).
// ---------------------------------------------------------------------------
#define T32B 8192                  // 128 rows x 64 bytes
#define CHUNKB (3 * T32B)          // A | Bh | Bl
#define SMEMB (2 * CHUNKB + 1024)

__global__ void __launch_bounds__(256, 2)
gemm_mma(const unsigned short* __restrict__ Wb, const float* __restrict__ bias,
         const float* __restrict__ res, float* __restrict__ out, int layer) {
    extern __shared__ char smraw[];
    __shared__ float s_stats[256];
    uint32_t sb0 = smem_u32(smraw);
    const uint32_t sb = (sb0 + 1023u) & ~1023u;

    const int tid = threadIdx.x;
    const int wid = tid >> 5;
    const int lane = tid & 31;
    const int rowBase = blockIdx.x * 128;
    const int do_stats = (layer < 3);

    s_stats[tid] = 0.f;

    const int r = tid >> 1;
    const int jb = (tid & 1) * 2;
    const int gnode = min(rowBase + r, NN - 1);
    const unsigned short* brow = Wb + (size_t)r * KW;

    const int warpM = wid >> 2;
    const int warpN = wid & 3;

    float acc[4][4][4];
#pragma unroll
    for (int mi = 0; mi < 4; mi++)
#pragma unroll
        for (int ni = 0; ni < 4; ni++)
#pragma unroll
            for (int q = 0; q < 4; q++) acc[mi][ni][q] = 0.f;

    const int a_row = warpM * 64 + ((lane >> 3) & 1) * 8 + (lane & 7);
    const int a_k8 = (lane >> 4) * 8;
    const int b_row = warpN * 32 + ((lane >> 4) & 1) * 8 + (lane & 7);
    const int b_k8 = ((lane >> 3) & 1) * 8;

#define LOAD_CHUNK(c, buf) do { \
        const uint32_t base = sb + (buf) * CHUNKB; \
        const int kg = (c) * 32; \
        const unsigned short* a = (kg < 256) \
            ? g_mhi + (size_t)gnode * 256 + kg \
            : g_hhi + (size_t)gnode * 128 + (kg - 256); \
        const unsigned short* bh = brow + (c) * 32; \
        const unsigned short* bl = brow + 384 + (c) * 32; \
        _Pragma("unroll") \
        for (int i = 0; i < 2; i++) { \
            const int j = jb + i; \
            const uint32_t sw = SWZ64(r * 64 + j * 16); \
            CP_ASYNC16(base + sw,             a + j * 8); \
            CP_ASYNC16(base + T32B + sw,      bh + j * 8); \
            CP_ASYNC16(base + 2 * T32B + sw,  bl + j * 8); \
        } \
        CP_COMMIT(); \
    } while (0)

    LOAD_CHUNK(0, 0);

#pragma unroll 1
    for (int c = 0; c < NCH; c++) {
        CP_WAIT0();
        __syncthreads();
        if (c + 1 < NCH) LOAD_CHUNK(c + 1, (c + 1) & 1);

        const uint32_t aT = sb + (c & 1) * CHUNKB;
        const uint32_t bH = aT + T32B;
        const uint32_t bL = aT + 2 * T32B;
#pragma unroll
        for (int k16 = 0; k16 < 2; k16++) {
            uint32_t afr[4][4], bhf[4][2], blf[4][2];
#pragma unroll
            for (int mi = 0; mi < 4; mi++) {
                const uint32_t addr = aT +
                    SWZ64((a_row + mi * 16) * 64 + (k16 * 16 + a_k8) * 2);
                asm volatile("ldmatrix.sync.aligned.m8n8.x4.shared.b16 "
                             "{%0,%1,%2,%3}, [%4];"
                             : "=r"(afr[mi][0]), "=r"(afr[mi][1]),
                               "=r"(afr[mi][2]), "=r"(afr[mi][3])
                             : "r"(addr));
            }
#pragma unroll
            for (int p = 0; p < 2; p++) {
                const uint32_t addr = bH +
                    SWZ64((b_row + p * 16) * 64 + (k16 * 16 + b_k8) * 2);
                asm volatile("ldmatrix.sync.aligned.m8n8.x4.shared.b16 "
                             "{%0,%1,%2,%3}, [%4];"
                             : "=r"(bhf[2 * p][0]), "=r"(bhf[2 * p][1]),
                               "=r"(bhf[2 * p + 1][0]), "=r"(bhf[2 * p + 1][1])
                             : "r"(addr));
            }
#pragma unroll
            for (int mi = 0; mi < 4; mi++)
#pragma unroll
                for (int ni = 0; ni < 4; ni++) {
                    asm volatile(
                        "mma.sync.aligned.m16n8k16.row.col.f32.f16.f16.f32 "
                        "{%0,%1,%2,%3}, {%4,%5,%6,%7}, {%8,%9}, {%0,%1,%2,%3};"
                        : "+f"(acc[mi][ni][0]), "+f"(acc[mi][ni][1]),
                          "+f"(acc[mi][ni][2]), "+f"(acc[mi][ni][3])
                        : "r"(afr[mi][0]), "r"(afr[mi][1]),
                          "r"(afr[mi][2]), "r"(afr[mi][3]),
                          "r"(bhf[ni][0]), "r"(bhf[ni][1]));
                }
#pragma unroll
            for (int p = 0; p < 2; p++) {
                const uint32_t addr = bL +
                    SWZ64((b_row + p * 16) * 64 + (k16 * 16 + b_k8) * 2);
                asm volatile("ldmatrix.sync.aligned.m8n8.x4.shared.b16 "
                             "{%0,%1,%2,%3}, [%4];"
                             : "=r"(blf[2 * p][0]), "=r"(blf[2 * p][1]),
                               "=r"(blf[2 * p + 1][0]), "=r"(blf[2 * p + 1][1])
                             : "r"(addr));
            }
#pragma unroll
            for (int mi = 0; mi < 4; mi++)
#pragma unroll
                for (int ni = 0; ni < 4; ni++) {
                    asm volatile(
                        "mma.sync.aligned.m16n8k16.row.col.f32.f16.f16.f32 "
                        "{%0,%1,%2,%3}, {%4,%5,%6,%7}, {%8,%9}, {%0,%1,%2,%3};"
                        : "+f"(acc[mi][ni][0]), "+f"(acc[mi][ni][1]),
                          "+f"(acc[mi][ni][2]), "+f"(acc[mi][ni][3])
                        : "r"(afr[mi][0]), "r"(afr[mi][1]),
                          "r"(afr[mi][2]), "r"(afr[mi][3]),
                          "r"(blf[ni][0]), "r"(blf[ni][1]));
                }
        }
    }
#undef LOAD_CHUNK

    // ---- epilogue: +bias, relu, +residual, stats ----
    const int mBase = rowBase + warpM * 64 + (lane >> 2);
    const int nBase = warpN * 32 + (lane & 3) * 2;
#pragma unroll
    for (int ni = 0; ni < 4; ni++) {
        const int n0 = nBase + ni * 8;
        const float2 bv = *(const float2*)(bias + n0);
        float cs0 = 0.f, cs1 = 0.f, cq0 = 0.f, cq1 = 0.f;
#pragma unroll
        for (int mi = 0; mi < 4; mi++) {
#pragma unroll
            for (int h = 0; h < 2; h++) {
                const int m = mBase + mi * 16 + h * 8;
                if (m < NN) {
                    float2 o;
                    o.x = fmaxf(acc[mi][ni][h * 2 + 0] + bv.x, 0.f);
                    o.y = fmaxf(acc[mi][ni][h * 2 + 1] + bv.y, 0.f);
                    if (res) {
                        const float2 rv = *(const float2*)(res + (size_t)m * NF + n0);
                        o.x += rv.x; o.y += rv.y;
                    }
                    *(float2*)(out + (size_t)m * NF + n0) = o;
                    cs0 += o.x; cs1 += o.y;
                    cq0 += o.x * o.x; cq1 += o.y * o.y;
                }
            }
        }
        if (do_stats) {
#pragma unroll
            for (int off = 4; off < 32; off <<= 1) {
                cs0 += __shfl_xor_sync(0xffffffffu, cs0, off);
                cs1 += __shfl_xor_sync(0xffffffffu, cs1, off);
                cq0 += __shfl_xor_sync(0xffffffffu, cq0, off);
                cq1 += __shfl_xor_sync(0xffffffffu, cq1, off);
            }
            if ((lane >> 2) == 0) {
                atomicAdd(&s_stats[n0], cs0);
                atomicAdd(&s_stats[n0 + 1], cs1);
                atomicAdd(&s_stats[128 + n0], cq0);
                atomicAdd(&s_stats[128 + n0 + 1], cq1);
            }
        }
    }
    if (do_stats) {
        __syncthreads();
        atomicAdd(&g_stats[layer + 1][tid], s_stats[tid]);
    }
}

// ---------------------------------------------------------------------------
extern "C" void kernel_launch(void* const* d_in, const int* in_sizes, int n_in,
                              void* d_out, int out_size) {
    const float* x = (const float*)d_in[0];
    const int* ei = (const int*)d_in[1];
    const int* et = (const int*)d_in[2];
    const float* W0rel = (const float*)d_in[3];
    const float* W0root = (const float*)d_in[4];
    const float* b0 = (const float*)d_in[5];
    const float* Wsrel = (const float*)d_in[6];
    const float* Wsroot = (const float*)d_in[7];
    const float* bs = (const float*)d_in[8];
    float* outp = (float*)d_out;

    const int* src = ei;
    const int* dst = ei + NE;

    void *p_stats = 0, *p_h = 0, *p_deg = 0, *p_wb = 0;
    cudaGetSymbolAddress(&p_stats, g_stats);
    cudaGetSymbolAddress(&p_h, g_h);
    cudaGetSymbolAddress(&p_deg, g_deg);
    cudaGetSymbolAddress(&p_wb, g_wb);

    static int smem_set = 0;
    if (!smem_set) {
        cudaFuncSetAttribute(gemm_mma, cudaFuncAttributeMaxDynamicSharedMemorySize, SMEMB);
        smem_set = 1;
    }

    // ---- fused prologue: zero + {hist | wt | stats}, then CSR tail ----
    cudaMemsetAsync(p_deg, 0, NSEG * sizeof(int));
    cudaMemsetAsync(p_stats, 0, 4 * 2 * NF * sizeof(float));
    prologue_kernel<<<PRO_BLKS, 256>>>(dst, et, W0rel, W0root, Wsrel, Wsroot, x);
    scan1_kernel<<<SCAN_BLKS, 256>>>();
    scan2_kernel<<<1, 128>>>();
    addoff_kernel<<<(NSEG + 255) / 256, 256>>>();
    fill_kernel<<<(NE + 255) / 256, 256>>>(src, dst, et);

    // ---- layers ----
    for (int c = 0; c < 4; c++) {
        const float* in = (c == 0) ? x : (const float*)p_h;
        const float* bb = (c == 0) ? b0 : bs + (c - 1) * NF;
        const float* res = (c == 0) ? (const float*)0 : (const float*)p_h;
        float* o = (c == 3) ? outp : (float*)p_h;
        const unsigned short* wb = (const unsigned short*)p_wb + (size_t)c * NF * KW;

        agg_kernel<<<(NSEG * 32 + 255) / 256, 256>>>(in, c);
        gemm_mma<<<(NN + 127) / 128, 256, SMEMB>>>(wb, bb, res, o, c);
    }
}